// round 5
// baseline (speedup 1.0000x reference)
#include <cuda_runtime.h>
#include <cstdint>
#include <cstddef>

// out[b,i,j] = W[words[b,i], words[b,j]]  (+ root[words[b,i]] when i==j)
// V=10000, B=8, N=2048
//
// R5: prepass is ONE multi-CTA kernel writing items into fixed-capacity
// per-row bins (no scan, no compaction). Main kernel (unchanged consumer
// core from R4): 1 producer warp walks vocab ids in warp-chunks, atomicExch
// read-and-resets counts (replay-safe), issues 5-deep TMA ring of 40KB rows;
// 16 consumer warps gather+store.

#define V 10000
#define B_DIM 8
#define N_DIM 2048
#define NITEMS (B_DIM * N_DIM)     // 16384
#define ROW_BYTES (V * 4)          // 40000
#define NSLOTS 5
#define CONSUMERS 512
#define THREADS (CONSUMERS + 32)
#define GRID_MAIN 152
#define CAP 64                     // max items per row (actual max ~12)

__device__ int d_cnt[V];               // zero-init; returned to zero each run
__device__ int d_items[V * CAP];
__device__ int d_wcursor;

// ================= prepass: count + place in one kernel =================
__global__ void place_kernel(const int* __restrict__ words)
{
    int k = blockIdx.x * blockDim.x + threadIdx.x;
    if (k == 0) d_wcursor = 0;         // reset main-kernel cursor each replay
    if (k < NITEMS) {
        int r = __ldg(words + k);
        int pos = atomicAdd(&d_cnt[r], 1);
        if (pos < CAP) d_items[r * CAP + pos] = k;
    }
}

// ================= mbarrier / TMA helpers =================
__device__ __forceinline__ void mbar_init(uint32_t mbar, uint32_t count) {
    asm volatile("mbarrier.init.shared.b64 [%0], %1;" :: "r"(mbar), "r"(count) : "memory");
}
__device__ __forceinline__ void mbar_expect_tx(uint32_t mbar, uint32_t bytes) {
    asm volatile("mbarrier.arrive.expect_tx.shared.b64 _, [%0], %1;"
                 :: "r"(mbar), "r"(bytes) : "memory");
}
__device__ __forceinline__ void mbar_arrive(uint32_t mbar) {
    asm volatile("mbarrier.arrive.shared.b64 _, [%0];" :: "r"(mbar) : "memory");
}
__device__ __forceinline__ void bulk_copy_g2s(uint32_t dst_smem, const void* src,
                                              uint32_t bytes, uint32_t mbar) {
    asm volatile("cp.async.bulk.shared::cta.global.mbarrier::complete_tx::bytes "
                 "[%0], [%1], %2, [%3];"
                 :: "r"(dst_smem), "l"(src), "r"(bytes), "r"(mbar) : "memory");
}
__device__ __forceinline__ void mbar_wait(uint32_t mbar, uint32_t phase) {
    asm volatile(
        "{\n\t"
        ".reg .pred P;\n\t"
        "WAIT_%=:\n\t"
        "mbarrier.try_wait.parity.acquire.cta.shared::cta.b64 P, [%0], %1, 0x989680;\n\t"
        "@P bra DONE_%=;\n\t"
        "bra WAIT_%=;\n\t"
        "DONE_%=:\n\t"
        "}"
        :: "r"(mbar), "r"(phase) : "memory");
}

// ================= main kernel =================
__global__ __launch_bounds__(THREADS) void pair_gather_ws_kernel(
    const int* __restrict__ words,
    const float* __restrict__ W,
    const float* __restrict__ root,
    float* __restrict__ out)
{
    extern __shared__ float sbuf[];   // NSLOTS * V floats, then barriers
    __shared__ int s_mr[NSLOTS], s_mb[NSLOTS], s_me[NSLOTS];

    const int t = threadIdx.x;
    const uint32_t smem_base = (uint32_t)__cvta_generic_to_shared(sbuf);
    const uint32_t bar_base  = smem_base + NSLOTS * ROW_BYTES;
    // full[s] = bar_base + s*16, empty[s] = bar_base + s*16 + 8

    if (t == 0) {
        #pragma unroll
        for (int s0 = 0; s0 < NSLOTS; ++s0) {
            mbar_init(bar_base + s0 * 16, 1);       // full: producer arrives
            mbar_init(bar_base + s0 * 16 + 8, 1);   // empty: one consumer arrives
        }
    }
    __syncthreads();

    if (t >= CONSUMERS) {
        // ---------------- producer warp ----------------
        const int lane = t - CONSUMERS;
        if (lane == 0)
            asm volatile("fence.proxy.async.shared::cta;" ::: "memory");
        __syncwarp();

        int k = 0;   // issued-slot counter (drives slot & phase)
        for (;;) {
            int base;
            if (lane == 0) base = atomicAdd(&d_wcursor, 32);
            base = __shfl_sync(0xFFFFFFFF, base, 0);
            if (base >= V) break;

            const int row = base + lane;
            int cnt = 0;
            if (row < V) cnt = atomicExch(&d_cnt[row], 0);   // read + reset
            if (cnt > CAP) cnt = CAP;
            unsigned mask = __ballot_sync(0xFFFFFFFF, cnt > 0);

            while (mask) {
                const int src = __ffs(mask) - 1;
                mask &= mask - 1;
                const int r = base + src;
                const int c = __shfl_sync(0xFFFFFFFF, cnt, src);

                const int slot = k % NSLOTS;
                const int n    = k / NSLOTS;
                ++k;
                if (lane == 0) {
                    mbar_wait(bar_base + slot * 16 + 8, (unsigned)((n & 1) ^ 1));
                    s_mr[slot] = r;
                    s_mb[slot] = r * CAP;
                    s_me[slot] = r * CAP + c;
                    mbar_expect_tx(bar_base + slot * 16, ROW_BYTES);
                    bulk_copy_g2s(smem_base + slot * ROW_BYTES,
                                  W + (size_t)r * V, ROW_BYTES,
                                  bar_base + slot * 16);
                }
            }
        }
        // sentinel
        if (lane == 0) {
            const int slot = k % NSLOTS;
            const int n    = k / NSLOTS;
            mbar_wait(bar_base + slot * 16 + 8, (unsigned)((n & 1) ^ 1));
            s_mr[slot] = -1;
            mbar_arrive(bar_base + slot * 16);
        }
    } else {
        // ---------------- consumer warps ----------------
        for (int k = 0;; ++k) {
            const int slot = k % NSLOTS;
            const int n    = k / NSLOTS;
            mbar_wait(bar_base + slot * 16, (unsigned)(n & 1));

            const int r = s_mr[slot];
            if (r < 0) break;
            const int b = s_mb[slot];
            const int e = s_me[slot];
            const float rootv = __ldg(root + r);
            const float* __restrict__ row = sbuf + (size_t)slot * V;

            for (int it = b; it < e; ++it) {
                const int blk = __ldg(d_items + it);   // b*N + i
                const int bb  = blk >> 11;
                const int i   = blk & (N_DIM - 1);
                const int4 c  = __ldg(reinterpret_cast<const int4*>(
                                         words + (size_t)bb * N_DIM) + t);
                const int j0 = t * 4;
                float4 v;
                v.x = row[c.x];
                v.y = row[c.y];
                v.z = row[c.z];
                v.w = row[c.w];
                const unsigned d = (unsigned)(i - j0);
                if (d < 4u) {
                    if      (d == 0u) v.x += rootv;
                    else if (d == 1u) v.y += rootv;
                    else if (d == 2u) v.z += rootv;
                    else              v.w += rootv;
                }
                *reinterpret_cast<float4*>(out + (size_t)blk * N_DIM + j0) = v;
            }

            asm volatile("bar.sync 1, %0;" :: "n"(CONSUMERS) : "memory");
            if (t == 0) mbar_arrive(bar_base + slot * 16 + 8);
        }
    }
}

// ================= launch =================
extern "C" void kernel_launch(void* const* d_in, const int* in_sizes, int n_in,
                              void* d_out, int out_size)
{
    const int*   words = (const int*)  d_in[0];
    const float* W     = (const float*)d_in[1];
    const float* root  = (const float*)d_in[2];
    float*       out   = (float*)d_out;

    static const size_t SMEM_DYN = (size_t)NSLOTS * ROW_BYTES + NSLOTS * 16;
    cudaFuncSetAttribute(pair_gather_ws_kernel,
                         cudaFuncAttributeMaxDynamicSharedMemorySize,
                         (int)SMEM_DYN);

    place_kernel<<<(NITEMS + 255) / 256, 256>>>(words);
    pair_gather_ws_kernel<<<GRID_MAIN, THREADS, SMEM_DYN>>>(words, W, root, out);
}

// round 6
// speedup vs baseline: 1.2299x; 1.2299x over previous
#include <cuda_runtime.h>
#include <cstdint>
#include <cstddef>

// out[b,i,j] = W[words[b,i], words[b,j]]  (+ root[words[b,i]] when i==j)
// V=10000, B=8, N=2048
//
// R6: R5 with the load-balance bug fixed. Prepass: one multi-CTA kernel
// binning items per row (fixed-capacity bins, no scan). Main kernel:
// producer warp grabs vocab ids in chunks of 4 (2500 chunks / 152 CTAs ->
// balanced), atomicExch read-and-resets the per-row count (replay-safe),
// keeps a 5-deep TMA ring of 40KB W rows full; 16 consumer warps
// gather+store output rows.

#define V 10000
#define B_DIM 8
#define N_DIM 2048
#define NITEMS (B_DIM * N_DIM)     // 16384
#define ROW_BYTES (V * 4)          // 40000
#define NSLOTS 5
#define CONSUMERS 512
#define THREADS (CONSUMERS + 32)
#define GRID_MAIN 152
#define CAP 64                     // max items per row (actual max ~12)
#define CHUNK 4                    // vocab ids per cursor grab

__device__ int d_cnt[V];           // zero-init; returned to zero every run
__device__ int d_items[V * CAP];
__device__ int d_wcursor;

// ================= prepass: count + place in one kernel =================
__global__ void place_kernel(const int* __restrict__ words)
{
    int k = blockIdx.x * blockDim.x + threadIdx.x;
    if (k == 0) d_wcursor = 0;         // reset main-kernel cursor each replay
    if (k < NITEMS) {
        int r = __ldg(words + k);
        int pos = atomicAdd(&d_cnt[r], 1);
        if (pos < CAP) d_items[r * CAP + pos] = k;
    }
}

// ================= mbarrier / TMA helpers =================
__device__ __forceinline__ void mbar_init(uint32_t mbar, uint32_t count) {
    asm volatile("mbarrier.init.shared.b64 [%0], %1;" :: "r"(mbar), "r"(count) : "memory");
}
__device__ __forceinline__ void mbar_expect_tx(uint32_t mbar, uint32_t bytes) {
    asm volatile("mbarrier.arrive.expect_tx.shared.b64 _, [%0], %1;"
                 :: "r"(mbar), "r"(bytes) : "memory");
}
__device__ __forceinline__ void mbar_arrive(uint32_t mbar) {
    asm volatile("mbarrier.arrive.shared.b64 _, [%0];" :: "r"(mbar) : "memory");
}
__device__ __forceinline__ void bulk_copy_g2s(uint32_t dst_smem, const void* src,
                                              uint32_t bytes, uint32_t mbar) {
    asm volatile("cp.async.bulk.shared::cta.global.mbarrier::complete_tx::bytes "
                 "[%0], [%1], %2, [%3];"
                 :: "r"(dst_smem), "l"(src), "r"(bytes), "r"(mbar) : "memory");
}
__device__ __forceinline__ void mbar_wait(uint32_t mbar, uint32_t phase) {
    asm volatile(
        "{\n\t"
        ".reg .pred P;\n\t"
        "WAIT_%=:\n\t"
        "mbarrier.try_wait.parity.acquire.cta.shared::cta.b64 P, [%0], %1, 0x989680;\n\t"
        "@P bra DONE_%=;\n\t"
        "bra WAIT_%=;\n\t"
        "DONE_%=:\n\t"
        "}"
        :: "r"(mbar), "r"(phase) : "memory");
}

// ================= main kernel =================
__global__ __launch_bounds__(THREADS) void pair_gather_ws_kernel(
    const int* __restrict__ words,
    const float* __restrict__ W,
    const float* __restrict__ root,
    float* __restrict__ out)
{
    extern __shared__ float sbuf[];   // NSLOTS * V floats, then barriers
    __shared__ int s_mr[NSLOTS], s_mb[NSLOTS], s_me[NSLOTS];

    const int t = threadIdx.x;
    const uint32_t smem_base = (uint32_t)__cvta_generic_to_shared(sbuf);
    const uint32_t bar_base  = smem_base + NSLOTS * ROW_BYTES;
    // full[s] = bar_base + s*16, empty[s] = bar_base + s*16 + 8

    if (t == 0) {
        #pragma unroll
        for (int s0 = 0; s0 < NSLOTS; ++s0) {
            mbar_init(bar_base + s0 * 16, 1);       // full: producer arrives
            mbar_init(bar_base + s0 * 16 + 8, 1);   // empty: one consumer arrives
        }
    }
    __syncthreads();

    if (t >= CONSUMERS) {
        // ---------------- producer warp ----------------
        const int lane = t - CONSUMERS;
        if (lane == 0)
            asm volatile("fence.proxy.async.shared::cta;" ::: "memory");
        __syncwarp();

        int k = 0;   // issued-slot counter (drives slot & phase)
        for (;;) {
            int base;
            if (lane == 0) base = atomicAdd(&d_wcursor, CHUNK);
            base = __shfl_sync(0xFFFFFFFF, base, 0);
            if (base >= V) break;

            const int row = base + lane;
            int cnt = 0;
            if (lane < CHUNK && row < V)
                cnt = atomicExch(&d_cnt[row], 0);    // read + reset (replay-safe)
            if (cnt > CAP) cnt = CAP;
            unsigned mask = __ballot_sync(0xFFFFFFFF, cnt > 0);

            while (mask) {
                const int src = __ffs(mask) - 1;
                mask &= mask - 1;
                const int r = base + src;
                const int c = __shfl_sync(0xFFFFFFFF, cnt, src);

                const int slot = k % NSLOTS;
                const int n    = k / NSLOTS;
                ++k;
                if (lane == 0) {
                    mbar_wait(bar_base + slot * 16 + 8, (unsigned)((n & 1) ^ 1));
                    s_mr[slot] = r;
                    s_mb[slot] = r * CAP;
                    s_me[slot] = r * CAP + c;
                    mbar_expect_tx(bar_base + slot * 16, ROW_BYTES);
                    bulk_copy_g2s(smem_base + slot * ROW_BYTES,
                                  W + (size_t)r * V, ROW_BYTES,
                                  bar_base + slot * 16);
                }
            }
        }
        // sentinel
        if (lane == 0) {
            const int slot = k % NSLOTS;
            const int n    = k / NSLOTS;
            mbar_wait(bar_base + slot * 16 + 8, (unsigned)((n & 1) ^ 1));
            s_mr[slot] = -1;
            mbar_arrive(bar_base + slot * 16);
        }
    } else {
        // ---------------- consumer warps ----------------
        for (int k = 0;; ++k) {
            const int slot = k % NSLOTS;
            const int n    = k / NSLOTS;
            mbar_wait(bar_base + slot * 16, (unsigned)(n & 1));

            const int r = s_mr[slot];
            if (r < 0) break;
            const int b = s_mb[slot];
            const int e = s_me[slot];
            const float rootv = __ldg(root + r);
            const float* __restrict__ row = sbuf + (size_t)slot * V;

            for (int it = b; it < e; ++it) {
                const int blk = __ldg(d_items + it);   // b*N + i
                const int bb  = blk >> 11;
                const int i   = blk & (N_DIM - 1);
                const int4 c  = __ldg(reinterpret_cast<const int4*>(
                                         words + (size_t)bb * N_DIM) + t);
                const int j0 = t * 4;
                float4 v;
                v.x = row[c.x];
                v.y = row[c.y];
                v.z = row[c.z];
                v.w = row[c.w];
                const unsigned d = (unsigned)(i - j0);
                if (d < 4u) {
                    if      (d == 0u) v.x += rootv;
                    else if (d == 1u) v.y += rootv;
                    else if (d == 2u) v.z += rootv;
                    else              v.w += rootv;
                }
                *reinterpret_cast<float4*>(out + (size_t)blk * N_DIM + j0) = v;
            }

            asm volatile("bar.sync 1, %0;" :: "n"(CONSUMERS) : "memory");
            if (t == 0) mbar_arrive(bar_base + slot * 16 + 8);
        }
    }
}

// ================= launch =================
extern "C" void kernel_launch(void* const* d_in, const int* in_sizes, int n_in,
                              void* d_out, int out_size)
{
    const int*   words = (const int*)  d_in[0];
    const float* W     = (const float*)d_in[1];
    const float* root  = (const float*)d_in[2];
    float*       out   = (float*)d_out;

    static const size_t SMEM_DYN = (size_t)NSLOTS * ROW_BYTES + NSLOTS * 16;
    cudaFuncSetAttribute(pair_gather_ws_kernel,
                         cudaFuncAttributeMaxDynamicSharedMemorySize,
                         (int)SMEM_DYN);

    place_kernel<<<(NITEMS + 255) / 256, 256>>>(words);
    pair_gather_ws_kernel<<<GRID_MAIN, THREADS, SMEM_DYN>>>(words, W, root, out);
}